// round 8
// baseline (speedup 1.0000x reference)
#include <cuda_runtime.h>
#include <cuda_bf16.h>

// Problem constants
#define NB    2
#define CCH   512
#define SSP   4096     // 64*64 spatial tokens
#define NH    8
#define HD    64
#define NHTOT (NB*NH)  // 16

// Q pre-scale: 1/sqrt(64) * log2(e)  (scores come out in log2 units)
#define QSCALE 0.18033688011f

// ---------------- scratch (static __device__, no allocations) ----------------
__device__ __align__(16) unsigned short g_xb[NB*CCH*SSP];   // x bf16, [n][c][s]
__device__ __align__(16) unsigned short g_W [4*CCH*CCH];    // Wq,Wk,Wv,Wo bf16
__device__ __align__(16) unsigned short g_Qt[NHTOT*SSP*HD]; // [n*8+h][s][d] (pre-scaled)
__device__ __align__(16) unsigned short g_Kt[NHTOT*SSP*HD]; // [n*8+h][s][d]
__device__ __align__(16) unsigned short g_Vc[NB*CCH*SSP];   // [n][c][s] (c = h*64+d)
__device__ __align__(16) unsigned short g_Oc[NB*CCH*SSP];   // attn out, [n][c][s]

// ---------------- helpers ----------------
__device__ __forceinline__ unsigned short f2bf(float v) {
    __nv_bfloat16 h = __float2bfloat16(v);
    return *reinterpret_cast<unsigned short*>(&h);
}
__device__ __forceinline__ unsigned pk2(float a, float b) {
    __nv_bfloat162 t = __floats2bfloat162_rn(a, b);
    return *reinterpret_cast<unsigned*>(&t);
}
__device__ __forceinline__ float ex2(float x) {
    float y;
    asm("ex2.approx.ftz.f32 %0, %1;" : "=f"(y) : "f"(x));
    return y;
}
__device__ __forceinline__ unsigned smem_u32(const void* p) {
    return (unsigned)__cvta_generic_to_shared(p);
}
__device__ __forceinline__ void sts16(unsigned addr, unsigned short v) {
    asm volatile("st.shared.u16 [%0], %1;" :: "r"(addr), "h"(v));
}
__device__ __forceinline__ void cpasync16(unsigned dst, const void* src) {
    asm volatile("cp.async.cg.shared.global [%0], [%1], 16;\n" :: "r"(dst), "l"(src));
}
__device__ __forceinline__ void cpcommit() {
    asm volatile("cp.async.commit_group;\n" ::: "memory");
}
template<int N> __device__ __forceinline__ void cpwait() {
    asm volatile("cp.async.wait_group %0;\n" :: "n"(N) : "memory");
}
__device__ __forceinline__ void ldsm_x4(unsigned& r0, unsigned& r1, unsigned& r2,
                                        unsigned& r3, unsigned addr) {
    asm volatile("ldmatrix.sync.aligned.m8n8.x4.shared.b16 {%0,%1,%2,%3}, [%4];"
        : "=r"(r0), "=r"(r1), "=r"(r2), "=r"(r3) : "r"(addr));
}
__device__ __forceinline__ void ldsm_x4_t(unsigned& r0, unsigned& r1, unsigned& r2,
                                          unsigned& r3, unsigned addr) {
    asm volatile("ldmatrix.sync.aligned.m8n8.x4.trans.shared.b16 {%0,%1,%2,%3}, [%4];"
        : "=r"(r0), "=r"(r1), "=r"(r2), "=r"(r3) : "r"(addr));
}
// D += A*B, m16n8k16 bf16 -> f32
__device__ __forceinline__ void mma16816(float* c,
        unsigned a0, unsigned a1, unsigned a2, unsigned a3,
        unsigned b0, unsigned b1) {
    asm volatile(
        "mma.sync.aligned.m16n8k16.row.col.f32.bf16.bf16.f32 "
        "{%0,%1,%2,%3},{%4,%5,%6,%7},{%8,%9},{%0,%1,%2,%3};\n"
        : "+f"(c[0]), "+f"(c[1]), "+f"(c[2]), "+f"(c[3])
        : "r"(a0), "r"(a1), "r"(a2), "r"(a3), "r"(b0), "r"(b1));
}

// ---------------- K0: fp32 -> bf16 pack ----------------
__global__ void convert_kernel(const float* __restrict__ x,
                               const float* __restrict__ wq, const float* __restrict__ wk,
                               const float* __restrict__ wv, const float* __restrict__ wo) {
    int stride = gridDim.x * blockDim.x;
    int t0 = blockIdx.x * blockDim.x + threadIdx.x;
    for (int i = t0; i < NB*CCH*SSP; i += stride) g_xb[i] = f2bf(x[i]);
    const int WSZ = CCH*CCH;
    for (int i = t0; i < WSZ; i += stride) {
        g_W[i]         = f2bf(wq[i]);
        g_W[WSZ + i]   = f2bf(wk[i]);
        g_W[2*WSZ + i] = f2bf(wv[i]);
        g_W[3*WSZ + i] = f2bf(wo[i]);
    }
}

// ---------------- K1/K3: persistent tiled GEMM ----------------
// phase 0: each CTA computes Q, K, V tiles for its (sT, cT): 24 slabs continuous pipeline.
// phase 1: single O tile per CTA (8 slabs).
// Tile 128x128, K-slab 64, 3-stage cp.async, one sync per slab.
#define GSTAGE 33792
#define G_SMEM (3*GSTAGE)
__global__ __launch_bounds__(256,2) void gemm_kernel(int phase,
        const float* __restrict__ bq, const float* __restrict__ bk,
        const float* __restrict__ bv, const float* __restrict__ bo,
        const float* __restrict__ x, const float* __restrict__ gamma,
        float* __restrict__ out) {
    extern __shared__ __align__(1024) unsigned char gsm[];
    unsigned smb = smem_u32(gsm);

    int n = blockIdx.z;
    int T = (phase == 0) ? 3 : 1;
    const unsigned short* Bm = (phase == 0) ? (g_xb + n*(CCH*SSP)) : (g_Oc + n*(CCH*SSP));

    int tid = threadIdx.x;
    int mBase = blockIdx.y * 128, sBase = blockIdx.x * 128;
    int warp = tid >> 5, lane = tid & 31, g = lane >> 2, qi = lane & 3;
    int wm = warp >> 1, wn = warp & 1;
    int lq = (lane & 7) + 8*((lane >> 3) & 1);
    int lc = 8*(lane >> 4);

    auto swA = [](int r, int k) -> unsigned {
        return (unsigned)(r*128 + ((2*k) ^ ((r & 7) << 4)));
    };

    float acc[2][8][4];
    #pragma unroll
    for (int a = 0; a < 2; a++)
        #pragma unroll
        for (int b = 0; b < 8; b++)
            #pragma unroll
            for (int c = 0; c < 4; c++) acc[a][b][c] = 0.f;

    auto stage = [&](int gI) {
        int t = gI >> 3, s = gI & 7;
        int which = (phase == 0) ? t : 3;
        const unsigned short* Wm = g_W + which * (CCH * CCH);
        unsigned ab = smb + (unsigned)(gI % 3) * (unsigned)GSTAGE;
        unsigned bb = ab + 16384u;
        int kc = s * 64;
        #pragma unroll
        for (int j = 0; j < 4; j++) {
            int u = tid + j*256;
            int ar = u >> 3, ak = (u & 7) * 8;
            cpasync16(ab + swA(ar, ak), &Wm[(size_t)(mBase + ar)*CCH + kc + ak]);
            int br = u >> 4, bc = (u & 15) * 8;
            cpasync16(bb + (unsigned)(br*136 + bc)*2u, &Bm[(size_t)(kc + br)*SSP + sBase + bc]);
        }
        cpcommit();
    };

    int NT = T * 8;
    stage(0);
    stage(1);

    for (int gI = 0; gI < NT; gI++) {
        if (gI < NT - 1) cpwait<1>(); else cpwait<0>();
        __syncthreads();
        if (gI + 2 < NT) stage(gI + 2);

        unsigned ab = smb + (unsigned)(gI % 3) * (unsigned)GSTAGE;
        unsigned bb = ab + 16384u;
        #pragma unroll
        for (int ks = 0; ks < 4; ks++) {
            int k0 = ks * 16;
            unsigned af[2][4], bf[8][2];
            #pragma unroll
            for (int mt = 0; mt < 2; mt++)
                ldsm_x4(af[mt][0], af[mt][1], af[mt][2], af[mt][3],
                        ab + swA(wm*32 + mt*16 + lq, k0 + lc));
            #pragma unroll
            for (int ng = 0; ng < 4; ng++) {
                unsigned r0, r1, r2, r3;
                ldsm_x4_t(r0, r1, r2, r3,
                        bb + (unsigned)((k0 + lq)*136 + wn*64 + ng*16 + lc)*2u);
                bf[2*ng][0] = r0;  bf[2*ng][1] = r1;
                bf[2*ng+1][0] = r2; bf[2*ng+1][1] = r3;
            }
            #pragma unroll
            for (int mt = 0; mt < 2; mt++)
                #pragma unroll
                for (int nt = 0; nt < 8; nt++)
                    mma16816(acc[mt][nt], af[mt][0], af[mt][1], af[mt][2], af[mt][3],
                             bf[nt][0], bf[nt][1]);
        }

        if ((gI & 7) == 7) {
            int t = gI >> 3;
            int which = (phase == 0) ? t : 3;
            unsigned scrOff = (unsigned)(gI % 3) * (unsigned)GSTAGE;  // just-consumed stage

            if (which <= 1) {
                // Q/K: smem-transpose epilogue, coalesced 16B stores.
                // BARRIER: all warps must finish ldsm-reading this stage before
                // we overwrite it as transpose scratch (R7 bug was missing this).
                __syncthreads();
                const float* bias = (which == 0) ? bq : bk;
                unsigned short* dst = (which == 0) ? g_Qt : g_Kt;
                float qs = (which == 0) ? QSCALE : 1.0f;
                float bA0 = bias[mBase + wm*32 + g];
                float bA1 = bias[mBase + wm*32 + g + 8];
                float bB0 = bias[mBase + wm*32 + 16 + g];
                float bB1 = bias[mBase + wm*32 + 16 + g + 8];
                #pragma unroll
                for (int p = 0; p < 2; p++) {
                    if (wn == p) {
                        #pragma unroll
                        for (int mt = 0; mt < 2; mt++) {
                            int r0 = wm*32 + mt*16 + g, r1 = r0 + 8;
                            float b0 = mt ? bB0 : bA0;
                            float b1 = mt ? bB1 : bA1;
                            #pragma unroll
                            for (int nt = 0; nt < 8; nt++) {
                                int sl = nt*8 + 2*qi;
                                unsigned base0 = smb + scrOff;
                                sts16(base0 + (unsigned)( sl     *136 + r0)*2u, f2bf((acc[mt][nt][0] + b0)*qs));
                                sts16(base0 + (unsigned)((sl + 1)*136 + r0)*2u, f2bf((acc[mt][nt][1] + b0)*qs));
                                sts16(base0 + (unsigned)( sl     *136 + r1)*2u, f2bf((acc[mt][nt][2] + b1)*qs));
                                sts16(base0 + (unsigned)((sl + 1)*136 + r1)*2u, f2bf((acc[mt][nt][3] + b1)*qs));
                            }
                        }
                    }
                    __syncthreads();
                    #pragma unroll
                    for (int r = 0; r < 4; r++) {
                        int u = tid + r*256;
                        int row = u >> 4, c = (u & 15) * 8;
                        int h = (mBase + c) >> 6;
                        int d = (mBase + c) & 63;
                        int srow = sBase + p*64 + row;
                        uint4 v = *(const uint4*)(gsm + scrOff + (unsigned)(row*136 + c)*2u);
                        *(uint4*)&dst[((size_t)(n*8 + h)*SSP + srow)*HD + d] = v;
                    }
                    __syncthreads();
                }
            } else if (which == 2) {
                // V: channel-major pair stores
                #pragma unroll
                for (int mt = 0; mt < 2; mt++) {
                    int o0 = mBase + wm*32 + mt*16 + g;
                    int o1 = o0 + 8;
                    float b0 = bv[o0], b1 = bv[o1];
                    #pragma unroll
                    for (int nt = 0; nt < 8; nt++) {
                        int s = sBase + wn*64 + nt*8 + 2*qi;
                        unsigned short* d0p = g_Vc + (n*CCH + o0) * SSP;
                        unsigned short* d1p = g_Vc + (n*CCH + o1) * SSP;
                        *(unsigned*)&d0p[s] = pk2(acc[mt][nt][0] + b0, acc[mt][nt][1] + b0);
                        *(unsigned*)&d1p[s] = pk2(acc[mt][nt][2] + b1, acc[mt][nt][3] + b1);
                    }
                }
            } else {
                // O: fp32 residual output
                float gm = gamma[0];
                #pragma unroll
                for (int mt = 0; mt < 2; mt++) {
                    int o0 = mBase + wm*32 + mt*16 + g;
                    int o1 = o0 + 8;
                    float b0 = bo[o0], b1 = bo[o1];
                    #pragma unroll
                    for (int nt = 0; nt < 8; nt++) {
                        int s = sBase + wn*64 + nt*8 + 2*qi;
                        int i0 = (n*CCH + o0) * SSP + s;
                        int i1 = (n*CCH + o1) * SSP + s;
                        out[i0]     = gm * (acc[mt][nt][0] + b0) + x[i0];
                        out[i0 + 1] = gm * (acc[mt][nt][1] + b0) + x[i0 + 1];
                        out[i1]     = gm * (acc[mt][nt][2] + b1) + x[i1];
                        out[i1 + 1] = gm * (acc[mt][nt][3] + b1) + x[i1 + 1];
                    }
                }
            }
            // reset accumulators for next tile
            #pragma unroll
            for (int a = 0; a < 2; a++)
                #pragma unroll
                for (int b = 0; b < 8; b++)
                    #pragma unroll
                    for (int c = 0; c < 4; c++) acc[a][b][c] = 0.f;
        }
    }
}

// ---------------- K2: flash attention, Br=128, Bc=64, d=64 ----------------
// 2 jobs per CTA (grid 256 = 1 wave). Q pre-scaled; softmax without running max.
// 3-stage cp.async pipeline, one sync per iteration.
#define FL_SMEM 65536
__global__ __launch_bounds__(256,2) void flash_kernel() {
    extern __shared__ __align__(1024) unsigned char smarr[];
    unsigned qb = smem_u32(smarr);
    unsigned kv = qb + 16384;   // stage s at kv + s*16384: [K 8192 | V 8192]

    int tid = threadIdx.x;
    int warp = tid >> 5, lane = tid & 31, g = lane >> 2, qi = lane & 3;
    int mrow = warp * 16;
    int lq  = (lane & 7) + 8*((lane >> 3) & 1);
    int lc  = 8*(lane >> 4);
    int lq2 = (lane & 7) + 8*(lane >> 4);
    int lc2 = 8*((lane >> 3) & 1);

    auto sw = [](int row, int ch) -> unsigned {
        return (unsigned)(row*128 + ((ch*2) ^ ((row & 7) << 4)));
    };

    for (int jj = 0; jj < 2; jj++) {
        int id = blockIdx.x + jj*256;
        int nh = id >> 5;
        int s0 = (id & 31) * 128;
        const unsigned short* Qg = g_Qt + (size_t)nh * (SSP*HD);
        const unsigned short* Kg = g_Kt + (size_t)nh * (SSP*HD);
        const unsigned short* Vg = g_Vc + (size_t)nh * (HD*SSP);

        // prologue: group0 = Q + stage0, group1 = stage1
        #pragma unroll
        for (int r = 0; r < 4; r++) {
            int u = tid + r*256; int row = u >> 3, c = (u & 7) * 8;
            cpasync16(qb + sw(row, c), &Qg[(size_t)(s0 + row)*HD + c]);
        }
        #pragma unroll
        for (int r = 0; r < 2; r++) {
            int u = tid + r*256; int row = u >> 3, c = (u & 7) * 8;
            cpasync16(kv + sw(row, c), &Kg[(size_t)row*HD + c]);
            cpasync16(kv + 8192u + sw(row, c), &Vg[(size_t)row*SSP + c]);
        }
        cpcommit();
        #pragma unroll
        for (int r = 0; r < 2; r++) {
            int u = tid + r*256; int row = u >> 3, c = (u & 7) * 8;
            cpasync16(kv + 16384u + sw(row, c), &Kg[(size_t)(64 + row)*HD + c]);
            cpasync16(kv + 16384u + 8192u + sw(row, c), &Vg[(size_t)row*SSP + 64 + c]);
        }
        cpcommit();

        float l0 = 0.f, l1 = 0.f;
        float o[8][4];
        #pragma unroll
        for (int a = 0; a < 8; a++)
            #pragma unroll
            for (int b = 0; b < 4; b++) o[a][b] = 0.f;

        for (int it = 0; it < 64; it++) {
            unsigned boff = (unsigned)(((unsigned)it) % 3u) * 16384u;
            if (it < 63) cpwait<1>(); else cpwait<0>();
            __syncthreads();
            if (it + 2 < 64) {
                unsigned nb = (unsigned)(((unsigned)(it + 2)) % 3u) * 16384u;
                int t1 = (it + 2) * 64;
                #pragma unroll
                for (int r = 0; r < 2; r++) {
                    int u = tid + r*256; int row = u >> 3, c = (u & 7) * 8;
                    cpasync16(kv + nb + sw(row, c), &Kg[(size_t)(t1 + row)*HD + c]);
                    cpasync16(kv + nb + 8192u + sw(row, c), &Vg[(size_t)row*SSP + t1 + c]);
                }
                cpcommit();
            }
            unsigned kb = kv + boff, vb = kv + boff + 8192u;

            // S = Q @ K^T (log2 units)
            float sc[8][4];
            #pragma unroll
            for (int a = 0; a < 8; a++)
                #pragma unroll
                for (int b = 0; b < 4; b++) sc[a][b] = 0.f;
            #pragma unroll
            for (int kk = 0; kk < 4; kk++) {
                int k0 = kk * 16;
                unsigned a0, a1, a2, a3;
                ldsm_x4(a0, a1, a2, a3, qb + sw(mrow + lq, k0 + lc));
                #pragma unroll
                for (int ng = 0; ng < 4; ng++) {
                    unsigned r0, r1, r2, r3;
                    ldsm_x4(r0, r1, r2, r3, kb + sw(ng*16 + lq2, k0 + lc2));
                    mma16816(sc[2*ng],     a0, a1, a2, a3, r0, r1);
                    mma16816(sc[2*ng + 1], a0, a1, a2, a3, r2, r3);
                }
            }

            // p = 2^s, accumulate row sums
            #pragma unroll
            for (int nt = 0; nt < 8; nt++) {
                sc[nt][0] = ex2(sc[nt][0]);
                sc[nt][1] = ex2(sc[nt][1]);
                sc[nt][2] = ex2(sc[nt][2]);
                sc[nt][3] = ex2(sc[nt][3]);
                l0 += sc[nt][0] + sc[nt][1];
                l1 += sc[nt][2] + sc[nt][3];
            }

            // O += P @ V
            #pragma unroll
            for (int kt = 0; kt < 4; kt++) {
                unsigned a0 = pk2(sc[2*kt    ][0], sc[2*kt    ][1]);
                unsigned a1 = pk2(sc[2*kt    ][2], sc[2*kt    ][3]);
                unsigned a2 = pk2(sc[2*kt + 1][0], sc[2*kt + 1][1]);
                unsigned a3 = pk2(sc[2*kt + 1][2], sc[2*kt + 1][3]);
                #pragma unroll
                for (int ng = 0; ng < 4; ng++) {
                    unsigned r0, r1, r2, r3;
                    ldsm_x4(r0, r1, r2, r3, vb + sw(ng*16 + lq2, kt*16 + lc2));
                    mma16816(o[2*ng],     a0, a1, a2, a3, r0, r1);
                    mma16816(o[2*ng + 1], a0, a1, a2, a3, r2, r3);
                }
            }
        }

        // row-sum reduce
        l0 += __shfl_xor_sync(0xffffffffu, l0, 1);
        l0 += __shfl_xor_sync(0xffffffffu, l0, 2);
        l1 += __shfl_xor_sync(0xffffffffu, l1, 1);
        l1 += __shfl_xor_sync(0xffffffffu, l1, 2);
        float inv0 = 1.f / l0, inv1 = 1.f / l1;

        // finalize + transpose via smem, write channel-major bf16
        __syncthreads();
        unsigned short* Os = (unsigned short*)smarr;   // 64*136 halves = 17408 B
        #pragma unroll
        for (int nt = 0; nt < 8; nt++) {
            int dv = nt*8 + 2*qi;
            Os[ dv     *136 + mrow + g    ] = f2bf(o[nt][0] * inv0);
            Os[(dv + 1)*136 + mrow + g    ] = f2bf(o[nt][1] * inv0);
            Os[ dv     *136 + mrow + g + 8] = f2bf(o[nt][2] * inv1);
            Os[(dv + 1)*136 + mrow + g + 8] = f2bf(o[nt][3] * inv1);
        }
        __syncthreads();
        unsigned short* Og = g_Oc + (size_t)nh * (HD*SSP) + s0;
        #pragma unroll
        for (int r = 0; r < 16; r++) {
            int u = tid + r*256; int dv = u >> 6, swc = u & 63;
            *(unsigned*)&Og[(size_t)dv*SSP + swc*2] = *(const unsigned*)&Os[dv*136 + swc*2];
        }
        __syncthreads();   // protect Q/Os region before next job's cp.async
    }
}

// ---------------- launch ----------------
extern "C" void kernel_launch(void* const* d_in, const int* in_sizes, int n_in,
                              void* d_out, int out_size) {
    const float* x     = (const float*)d_in[0];
    const float* Wq    = (const float*)d_in[1];
    const float* bq    = (const float*)d_in[2];
    const float* Wk    = (const float*)d_in[3];
    const float* bk    = (const float*)d_in[4];
    const float* Wv    = (const float*)d_in[5];
    const float* bv    = (const float*)d_in[6];
    const float* Wo    = (const float*)d_in[7];
    const float* bo    = (const float*)d_in[8];
    const float* gamma = (const float*)d_in[9];
    float* out = (float*)d_out;

    cudaFuncSetAttribute(flash_kernel,
        cudaFuncAttributeMaxDynamicSharedMemorySize, FL_SMEM);
    cudaFuncSetAttribute(gemm_kernel,
        cudaFuncAttributeMaxDynamicSharedMemorySize, G_SMEM);

    convert_kernel<<<1024, 256>>>(x, Wq, Wk, Wv, Wo);
    gemm_kernel<<<dim3(SSP/128, CCH/128, NB), 256, G_SMEM>>>(0, bq, bk, bv, bo, x, gamma, out);
    flash_kernel<<<256, 256, FL_SMEM>>>();
    gemm_kernel<<<dim3(SSP/128, CCH/128, NB), 256, G_SMEM>>>(1, bq, bk, bv, bo, x, gamma, out);
}

// round 9
// speedup vs baseline: 1.0375x; 1.0375x over previous
#include <cuda_runtime.h>
#include <cuda_bf16.h>

// Problem constants
#define NB    2
#define CCH   512
#define SSP   4096     // 64*64 spatial tokens
#define NH    8
#define HD    64
#define NHTOT (NB*NH)  // 16

// Q pre-scale: 1/sqrt(64) * log2(e)  (scores come out in log2 units)
#define QSCALE 0.18033688011f

// ---------------- scratch (static __device__, no allocations) ----------------
__device__ __align__(16) unsigned short g_xb[NB*CCH*SSP];   // x bf16, [n][c][s]
__device__ __align__(16) unsigned short g_W [4*CCH*CCH];    // Wq,Wk,Wv,Wo bf16
__device__ __align__(16) unsigned short g_Qt[NHTOT*SSP*HD]; // [n*8+h][s][d] (pre-scaled)
__device__ __align__(16) unsigned short g_Kt[NHTOT*SSP*HD]; // [n*8+h][s][d]
__device__ __align__(16) unsigned short g_Vc[NB*CCH*SSP];   // [n][c][s] (c = h*64+d)
__device__ __align__(16) unsigned short g_Oc[NB*CCH*SSP];   // attn out, [n][c][s]

// ---------------- helpers ----------------
__device__ __forceinline__ unsigned short f2bf(float v) {
    __nv_bfloat16 h = __float2bfloat16(v);
    return *reinterpret_cast<unsigned short*>(&h);
}
__device__ __forceinline__ unsigned pk2(float a, float b) {
    __nv_bfloat162 t = __floats2bfloat162_rn(a, b);
    return *reinterpret_cast<unsigned*>(&t);
}
__device__ __forceinline__ float ex2(float x) {
    float y;
    asm("ex2.approx.ftz.f32 %0, %1;" : "=f"(y) : "f"(x));
    return y;
}
__device__ __forceinline__ unsigned smem_u32(const void* p) {
    return (unsigned)__cvta_generic_to_shared(p);
}
__device__ __forceinline__ void sts16(unsigned addr, unsigned short v) {
    asm volatile("st.shared.u16 [%0], %1;" :: "r"(addr), "h"(v));
}
__device__ __forceinline__ void cpasync16(unsigned dst, const void* src) {
    asm volatile("cp.async.cg.shared.global [%0], [%1], 16;\n" :: "r"(dst), "l"(src));
}
__device__ __forceinline__ void cpcommit() {
    asm volatile("cp.async.commit_group;\n" ::: "memory");
}
template<int N> __device__ __forceinline__ void cpwait() {
    asm volatile("cp.async.wait_group %0;\n" :: "n"(N) : "memory");
}
__device__ __forceinline__ void ldsm_x4(unsigned& r0, unsigned& r1, unsigned& r2,
                                        unsigned& r3, unsigned addr) {
    asm volatile("ldmatrix.sync.aligned.m8n8.x4.shared.b16 {%0,%1,%2,%3}, [%4];"
        : "=r"(r0), "=r"(r1), "=r"(r2), "=r"(r3) : "r"(addr));
}
__device__ __forceinline__ void ldsm_x4_t(unsigned& r0, unsigned& r1, unsigned& r2,
                                          unsigned& r3, unsigned addr) {
    asm volatile("ldmatrix.sync.aligned.m8n8.x4.trans.shared.b16 {%0,%1,%2,%3}, [%4];"
        : "=r"(r0), "=r"(r1), "=r"(r2), "=r"(r3) : "r"(addr));
}
// D += A*B, m16n8k16 bf16 -> f32
__device__ __forceinline__ void mma16816(float* c,
        unsigned a0, unsigned a1, unsigned a2, unsigned a3,
        unsigned b0, unsigned b1) {
    asm volatile(
        "mma.sync.aligned.m16n8k16.row.col.f32.bf16.bf16.f32 "
        "{%0,%1,%2,%3},{%4,%5,%6,%7},{%8,%9},{%0,%1,%2,%3};\n"
        : "+f"(c[0]), "+f"(c[1]), "+f"(c[2]), "+f"(c[3])
        : "r"(a0), "r"(a1), "r"(a2), "r"(a3), "r"(b0), "r"(b1));
}

// ---------------- K0: fp32 -> bf16 pack ----------------
__global__ void convert_kernel(const float* __restrict__ x,
                               const float* __restrict__ wq, const float* __restrict__ wk,
                               const float* __restrict__ wv, const float* __restrict__ wo) {
    int stride = gridDim.x * blockDim.x;
    int t0 = blockIdx.x * blockDim.x + threadIdx.x;
    for (int i = t0; i < NB*CCH*SSP; i += stride) g_xb[i] = f2bf(x[i]);
    const int WSZ = CCH*CCH;
    for (int i = t0; i < WSZ; i += stride) {
        g_W[i]         = f2bf(wq[i]);
        g_W[WSZ + i]   = f2bf(wk[i]);
        g_W[2*WSZ + i] = f2bf(wv[i]);
        g_W[3*WSZ + i] = f2bf(wo[i]);
    }
}

// ---------------- K1/K3: tiled GEMM  Out[o,s] = W[o,:] @ B[:,s] + bias ----------------
// phase 0: blockIdx.z = which*2 + n (which: 0=Q,1=K,2=V), 768 CTAs. phase 1: z=n, 256 CTAs.
// Tile 128x128, K-slab 64, 3-stage cp.async, one sync per slab.
// Q/K epilogue: smem-transpose (scratch = stage 0) + coalesced uint4 stores.
#define GSTAGE 33792
#define G_SMEM (3*GSTAGE)
__global__ __launch_bounds__(256,2) void gemm_kernel(int phase,
        const float* __restrict__ bq, const float* __restrict__ bk,
        const float* __restrict__ bv, const float* __restrict__ bo,
        const float* __restrict__ x, const float* __restrict__ gamma,
        float* __restrict__ out) {
    extern __shared__ __align__(1024) unsigned char gsm[];
    unsigned smb = smem_u32(gsm);

    int which, n;
    const unsigned short* Bm;
    if (phase == 0) {
        int z = blockIdx.z; which = z >> 1; n = z & 1;
        Bm = g_xb + n * (CCH * SSP);
    } else {
        which = 3; n = blockIdx.z;
        Bm = g_Oc + n * (CCH * SSP);
    }
    const unsigned short* Wm = g_W + which * (CCH * CCH);

    int tid = threadIdx.x;
    int mBase = blockIdx.y * 128, sBase = blockIdx.x * 128;
    int warp = tid >> 5, lane = tid & 31, g = lane >> 2, qi = lane & 3;
    int wm = warp >> 1, wn = warp & 1;
    int lq = (lane & 7) + 8*((lane >> 3) & 1);
    int lc = 8*(lane >> 4);

    auto swA = [](int r, int k) -> unsigned {
        return (unsigned)(r*128 + ((2*k) ^ ((r & 7) << 4)));
    };

    float acc[2][8][4];
    #pragma unroll
    for (int a = 0; a < 2; a++)
        #pragma unroll
        for (int b = 0; b < 8; b++)
            #pragma unroll
            for (int c = 0; c < 4; c++) acc[a][b][c] = 0.f;

    auto stage = [&](int s) {
        unsigned ab = smb + (unsigned)(s % 3) * (unsigned)GSTAGE;
        unsigned bb = ab + 16384u;
        int kc = s * 64;
        #pragma unroll
        for (int j = 0; j < 4; j++) {
            int u = tid + j*256;
            int ar = u >> 3, ak = (u & 7) * 8;
            cpasync16(ab + swA(ar, ak), &Wm[(size_t)(mBase + ar)*CCH + kc + ak]);
            int br = u >> 4, bc = (u & 15) * 8;
            cpasync16(bb + (unsigned)(br*136 + bc)*2u, &Bm[(size_t)(kc + br)*SSP + sBase + bc]);
        }
        cpcommit();
    };

    stage(0);
    stage(1);

    for (int s = 0; s < 8; s++) {
        if (s < 7) cpwait<1>(); else cpwait<0>();
        __syncthreads();
        if (s + 2 < 8) stage(s + 2);

        unsigned ab = smb + (unsigned)(s % 3) * (unsigned)GSTAGE;
        unsigned bb = ab + 16384u;
        #pragma unroll
        for (int ks = 0; ks < 4; ks++) {
            int k0 = ks * 16;
            unsigned af[2][4], bf[8][2];
            #pragma unroll
            for (int mt = 0; mt < 2; mt++)
                ldsm_x4(af[mt][0], af[mt][1], af[mt][2], af[mt][3],
                        ab + swA(wm*32 + mt*16 + lq, k0 + lc));
            #pragma unroll
            for (int ng = 0; ng < 4; ng++) {
                unsigned r0, r1, r2, r3;
                ldsm_x4_t(r0, r1, r2, r3,
                        bb + (unsigned)((k0 + lq)*136 + wn*64 + ng*16 + lc)*2u);
                bf[2*ng][0] = r0;  bf[2*ng][1] = r1;
                bf[2*ng+1][0] = r2; bf[2*ng+1][1] = r3;
            }
            #pragma unroll
            for (int mt = 0; mt < 2; mt++)
                #pragma unroll
                for (int nt = 0; nt < 8; nt++)
                    mma16816(acc[mt][nt], af[mt][0], af[mt][1], af[mt][2], af[mt][3],
                             bf[nt][0], bf[nt][1]);
        }
    }

    // ---------------- epilogue ----------------
    if (which <= 1) {
        // Q/K: smem-transpose epilogue into stage-0 buffer (its ldsm reads all
        // completed before the top-of-slab-7 barrier), coalesced 16B stores.
        const float* bias = (which == 0) ? bq : bk;
        unsigned short* dst = (which == 0) ? g_Qt : g_Kt;
        float qs = (which == 0) ? QSCALE : 1.0f;
        float bA0 = bias[mBase + wm*32 + g];
        float bA1 = bias[mBase + wm*32 + g + 8];
        float bB0 = bias[mBase + wm*32 + 16 + g];
        float bB1 = bias[mBase + wm*32 + 16 + g + 8];
        #pragma unroll
        for (int p = 0; p < 2; p++) {
            if (wn == p) {
                #pragma unroll
                for (int mt = 0; mt < 2; mt++) {
                    int r0 = wm*32 + mt*16 + g, r1 = r0 + 8;
                    float b0 = mt ? bB0 : bA0;
                    float b1 = mt ? bB1 : bA1;
                    #pragma unroll
                    for (int nt = 0; nt < 8; nt++) {
                        int sl = nt*8 + 2*qi;
                        sts16(smb + (unsigned)( sl     *136 + r0)*2u, f2bf((acc[mt][nt][0] + b0)*qs));
                        sts16(smb + (unsigned)((sl + 1)*136 + r0)*2u, f2bf((acc[mt][nt][1] + b0)*qs));
                        sts16(smb + (unsigned)( sl     *136 + r1)*2u, f2bf((acc[mt][nt][2] + b1)*qs));
                        sts16(smb + (unsigned)((sl + 1)*136 + r1)*2u, f2bf((acc[mt][nt][3] + b1)*qs));
                    }
                }
            }
            __syncthreads();
            #pragma unroll
            for (int r = 0; r < 4; r++) {
                int u = tid + r*256;
                int row = u >> 4, c = (u & 15) * 8;
                int h = (mBase + c) >> 6;
                int d = (mBase + c) & 63;
                int srow = sBase + p*64 + row;
                uint4 v = *(const uint4*)(gsm + (unsigned)(row*136 + c)*2u);
                *(uint4*)&dst[((size_t)(n*8 + h)*SSP + srow)*HD + d] = v;
            }
            __syncthreads();
        }
    } else if (which == 2) {
        // V: channel-major pair stores
        #pragma unroll
        for (int mt = 0; mt < 2; mt++) {
            int o0 = mBase + wm*32 + mt*16 + g;
            int o1 = o0 + 8;
            float b0 = bv[o0], b1 = bv[o1];
            #pragma unroll
            for (int nt = 0; nt < 8; nt++) {
                int s = sBase + wn*64 + nt*8 + 2*qi;
                unsigned short* d0p = g_Vc + (n*CCH + o0) * SSP;
                unsigned short* d1p = g_Vc + (n*CCH + o1) * SSP;
                *(unsigned*)&d0p[s] = pk2(acc[mt][nt][0] + b0, acc[mt][nt][1] + b0);
                *(unsigned*)&d1p[s] = pk2(acc[mt][nt][2] + b1, acc[mt][nt][3] + b1);
            }
        }
    } else {
        // O: fp32 residual output
        float gm = gamma[0];
        #pragma unroll
        for (int mt = 0; mt < 2; mt++) {
            int o0 = mBase + wm*32 + mt*16 + g;
            int o1 = o0 + 8;
            float b0 = bo[o0], b1 = bo[o1];
            #pragma unroll
            for (int nt = 0; nt < 8; nt++) {
                int s = sBase + wn*64 + nt*8 + 2*qi;
                int i0 = (n*CCH + o0) * SSP + s;
                int i1 = (n*CCH + o1) * SSP + s;
                out[i0]     = gm * (acc[mt][nt][0] + b0) + x[i0];
                out[i0 + 1] = gm * (acc[mt][nt][1] + b0) + x[i0 + 1];
                out[i1]     = gm * (acc[mt][nt][2] + b1) + x[i1];
                out[i1 + 1] = gm * (acc[mt][nt][3] + b1) + x[i1 + 1];
            }
        }
    }
}

// ---------------- K2: flash attention, Br=128, Bc=64, d=64 ----------------
// 512 CTAs (over-subscribed grid; resident pairs hide each other's stalls).
// Q pre-scaled; softmax without running max; 3-stage cp.async, one sync/iter.
#define FL_SMEM 65536
__global__ __launch_bounds__(256,2) void flash_kernel() {
    extern __shared__ __align__(1024) unsigned char smarr[];
    unsigned qb = smem_u32(smarr);
    unsigned kv = qb + 16384;   // stage s at kv + s*16384: [K 8192 | V 8192]

    int tid = threadIdx.x;
    int nh = blockIdx.y;            // n*8 + h
    int s0 = blockIdx.x * 128;
    const unsigned short* Qg = g_Qt + (size_t)nh * (SSP*HD);
    const unsigned short* Kg = g_Kt + (size_t)nh * (SSP*HD);
    const unsigned short* Vg = g_Vc + (size_t)nh * (HD*SSP);

    int warp = tid >> 5, lane = tid & 31, g = lane >> 2, qi = lane & 3;
    int mrow = warp * 16;
    int lq  = (lane & 7) + 8*((lane >> 3) & 1);
    int lc  = 8*(lane >> 4);
    int lq2 = (lane & 7) + 8*(lane >> 4);
    int lc2 = 8*((lane >> 3) & 1);

    auto sw = [](int row, int ch) -> unsigned {
        return (unsigned)(row*128 + ((ch*2) ^ ((row & 7) << 4)));
    };

    // prologue: group0 = Q + stage0, group1 = stage1
    #pragma unroll
    for (int r = 0; r < 4; r++) {
        int u = tid + r*256; int row = u >> 3, c = (u & 7) * 8;
        cpasync16(qb + sw(row, c), &Qg[(size_t)(s0 + row)*HD + c]);
    }
    #pragma unroll
    for (int r = 0; r < 2; r++) {
        int u = tid + r*256; int row = u >> 3, c = (u & 7) * 8;
        cpasync16(kv + sw(row, c), &Kg[(size_t)row*HD + c]);
        cpasync16(kv + 8192u + sw(row, c), &Vg[(size_t)row*SSP + c]);
    }
    cpcommit();
    #pragma unroll
    for (int r = 0; r < 2; r++) {
        int u = tid + r*256; int row = u >> 3, c = (u & 7) * 8;
        cpasync16(kv + 16384u + sw(row, c), &Kg[(size_t)(64 + row)*HD + c]);
        cpasync16(kv + 16384u + 8192u + sw(row, c), &Vg[(size_t)row*SSP + 64 + c]);
    }
    cpcommit();

    float l0 = 0.f, l1 = 0.f;
    float o[8][4];
    #pragma unroll
    for (int a = 0; a < 8; a++)
        #pragma unroll
        for (int b = 0; b < 4; b++) o[a][b] = 0.f;

    for (int it = 0; it < 64; it++) {
        unsigned boff = (unsigned)(((unsigned)it) % 3u) * 16384u;
        if (it < 63) cpwait<1>(); else cpwait<0>();
        __syncthreads();
        if (it + 2 < 64) {
            unsigned nb = (unsigned)(((unsigned)(it + 2)) % 3u) * 16384u;
            int t1 = (it + 2) * 64;
            #pragma unroll
            for (int r = 0; r < 2; r++) {
                int u = tid + r*256; int row = u >> 3, c = (u & 7) * 8;
                cpasync16(kv + nb + sw(row, c), &Kg[(size_t)(t1 + row)*HD + c]);
                cpasync16(kv + nb + 8192u + sw(row, c), &Vg[(size_t)row*SSP + t1 + c]);
            }
            cpcommit();
        }
        unsigned kb = kv + boff, vb = kv + boff + 8192u;

        // S = Q @ K^T (log2 units)
        float sc[8][4];
        #pragma unroll
        for (int a = 0; a < 8; a++)
            #pragma unroll
            for (int b = 0; b < 4; b++) sc[a][b] = 0.f;
        #pragma unroll
        for (int kk = 0; kk < 4; kk++) {
            int k0 = kk * 16;
            unsigned a0, a1, a2, a3;
            ldsm_x4(a0, a1, a2, a3, qb + sw(mrow + lq, k0 + lc));
            #pragma unroll
            for (int ng = 0; ng < 4; ng++) {
                unsigned r0, r1, r2, r3;
                ldsm_x4(r0, r1, r2, r3, kb + sw(ng*16 + lq2, k0 + lc2));
                mma16816(sc[2*ng],     a0, a1, a2, a3, r0, r1);
                mma16816(sc[2*ng + 1], a0, a1, a2, a3, r2, r3);
            }
        }

        // p = 2^s, accumulate per-thread row sums
        #pragma unroll
        for (int nt = 0; nt < 8; nt++) {
            sc[nt][0] = ex2(sc[nt][0]);
            sc[nt][1] = ex2(sc[nt][1]);
            sc[nt][2] = ex2(sc[nt][2]);
            sc[nt][3] = ex2(sc[nt][3]);
            l0 += sc[nt][0] + sc[nt][1];
            l1 += sc[nt][2] + sc[nt][3];
        }

        // O += P @ V
        #pragma unroll
        for (int kt = 0; kt < 4; kt++) {
            unsigned a0 = pk2(sc[2*kt    ][0], sc[2*kt    ][1]);
            unsigned a1 = pk2(sc[2*kt    ][2], sc[2*kt    ][3]);
            unsigned a2 = pk2(sc[2*kt + 1][0], sc[2*kt + 1][1]);
            unsigned a3 = pk2(sc[2*kt + 1][2], sc[2*kt + 1][3]);
            #pragma unroll
            for (int ng = 0; ng < 4; ng++) {
                unsigned r0, r1, r2, r3;
                ldsm_x4(r0, r1, r2, r3, vb + sw(ng*16 + lq2, kt*16 + lc2));
                mma16816(o[2*ng],     a0, a1, a2, a3, r0, r1);
                mma16816(o[2*ng + 1], a0, a1, a2, a3, r2, r3);
            }
        }
    }

    // row-sum reduce (deferred out of the loop)
    l0 += __shfl_xor_sync(0xffffffffu, l0, 1);
    l0 += __shfl_xor_sync(0xffffffffu, l0, 2);
    l1 += __shfl_xor_sync(0xffffffffu, l1, 1);
    l1 += __shfl_xor_sync(0xffffffffu, l1, 2);
    float inv0 = 1.f / l0, inv1 = 1.f / l1;

    // finalize + transpose via smem, write channel-major bf16
    __syncthreads();
    unsigned short* Os = (unsigned short*)smarr;   // 64*136 halves = 17408 B
    #pragma unroll
    for (int nt = 0; nt < 8; nt++) {
        int dv = nt*8 + 2*qi;
        Os[ dv     *136 + mrow + g    ] = f2bf(o[nt][0] * inv0);
        Os[(dv + 1)*136 + mrow + g    ] = f2bf(o[nt][1] * inv0);
        Os[ dv     *136 + mrow + g + 8] = f2bf(o[nt][2] * inv1);
        Os[(dv + 1)*136 + mrow + g + 8] = f2bf(o[nt][3] * inv1);
    }
    __syncthreads();
    unsigned short* Og = g_Oc + (size_t)nh * (HD*SSP) + s0;
    #pragma unroll
    for (int r = 0; r < 16; r++) {
        int u = tid + r*256; int dv = u >> 6, swc = u & 63;
        *(unsigned*)&Og[(size_t)dv*SSP + swc*2] = *(const unsigned*)&Os[dv*136 + swc*2];
    }
}

// ---------------- launch ----------------
extern "C" void kernel_launch(void* const* d_in, const int* in_sizes, int n_in,
                              void* d_out, int out_size) {
    const float* x     = (const float*)d_in[0];
    const float* Wq    = (const float*)d_in[1];
    const float* bq    = (const float*)d_in[2];
    const float* Wk    = (const float*)d_in[3];
    const float* bk    = (const float*)d_in[4];
    const float* Wv    = (const float*)d_in[5];
    const float* bv    = (const float*)d_in[6];
    const float* Wo    = (const float*)d_in[7];
    const float* bo    = (const float*)d_in[8];
    const float* gamma = (const float*)d_in[9];
    float* out = (float*)d_out;

    cudaFuncSetAttribute(flash_kernel,
        cudaFuncAttributeMaxDynamicSharedMemorySize, FL_SMEM);
    cudaFuncSetAttribute(gemm_kernel,
        cudaFuncAttributeMaxDynamicSharedMemorySize, G_SMEM);

    convert_kernel<<<1024, 256>>>(x, Wq, Wk, Wv, Wo);
    gemm_kernel<<<dim3(SSP/128, CCH/128, 6), 256, G_SMEM>>>(0, bq, bk, bv, bo, x, gamma, out);
    flash_kernel<<<dim3(SSP/128, NHTOT), 256, FL_SMEM>>>();
    gemm_kernel<<<dim3(SSP/128, CCH/128, NB), 256, G_SMEM>>>(1, bq, bk, bv, bo, x, gamma, out);
}

// round 10
// speedup vs baseline: 1.0901x; 1.0506x over previous
#include <cuda_runtime.h>
#include <cuda_bf16.h>

// Problem constants
#define NB    2
#define CCH   512
#define SSP   4096     // 64*64 spatial tokens
#define NH    8
#define HD    64
#define NHTOT (NB*NH)  // 16

// Q pre-scale: 1/sqrt(64) * log2(e)  (scores come out in log2 units)
#define QSCALE 0.18033688011f
// bf16 1.0 pair (ones B-fragment for row-sum MMA)
#define ONES2  0x3F803F80u

// ---------------- scratch (static __device__, no allocations) ----------------
__device__ __align__(16) unsigned short g_xb[NB*CCH*SSP];   // x bf16, [n][c][s]
__device__ __align__(16) unsigned short g_W [4*CCH*CCH];    // Wq,Wk,Wv,Wo bf16
__device__ __align__(16) unsigned short g_Qt[NHTOT*SSP*HD]; // [n*8+h][s][d] (pre-scaled)
__device__ __align__(16) unsigned short g_Kt[NHTOT*SSP*HD]; // [n*8+h][s][d]
__device__ __align__(16) unsigned short g_Vc[NB*CCH*SSP];   // [n][c][s] (c = h*64+d)
__device__ __align__(16) unsigned short g_Oc[NB*CCH*SSP];   // attn out, [n][c][s]

// ---------------- helpers ----------------
__device__ __forceinline__ unsigned short f2bf(float v) {
    __nv_bfloat16 h = __float2bfloat16(v);
    return *reinterpret_cast<unsigned short*>(&h);
}
__device__ __forceinline__ unsigned pk2(float a, float b) {
    __nv_bfloat162 t = __floats2bfloat162_rn(a, b);
    return *reinterpret_cast<unsigned*>(&t);
}
__device__ __forceinline__ float ex2(float x) {
    float y;
    asm("ex2.approx.ftz.f32 %0, %1;" : "=f"(y) : "f"(x));
    return y;
}
__device__ __forceinline__ unsigned smem_u32(const void* p) {
    return (unsigned)__cvta_generic_to_shared(p);
}
__device__ __forceinline__ void sts16(unsigned addr, unsigned short v) {
    asm volatile("st.shared.u16 [%0], %1;" :: "r"(addr), "h"(v));
}
__device__ __forceinline__ void cpasync16(unsigned dst, const void* src) {
    asm volatile("cp.async.cg.shared.global [%0], [%1], 16;\n" :: "r"(dst), "l"(src));
}
__device__ __forceinline__ void cpcommit() {
    asm volatile("cp.async.commit_group;\n" ::: "memory");
}
template<int N> __device__ __forceinline__ void cpwait() {
    asm volatile("cp.async.wait_group %0;\n" :: "n"(N) : "memory");
}
__device__ __forceinline__ void ldsm_x4(unsigned& r0, unsigned& r1, unsigned& r2,
                                        unsigned& r3, unsigned addr) {
    asm volatile("ldmatrix.sync.aligned.m8n8.x4.shared.b16 {%0,%1,%2,%3}, [%4];"
        : "=r"(r0), "=r"(r1), "=r"(r2), "=r"(r3) : "r"(addr));
}
__device__ __forceinline__ void ldsm_x4_t(unsigned& r0, unsigned& r1, unsigned& r2,
                                          unsigned& r3, unsigned addr) {
    asm volatile("ldmatrix.sync.aligned.m8n8.x4.trans.shared.b16 {%0,%1,%2,%3}, [%4];"
        : "=r"(r0), "=r"(r1), "=r"(r2), "=r"(r3) : "r"(addr));
}
// D += A*B, m16n8k16 bf16 -> f32
__device__ __forceinline__ void mma16816(float* c,
        unsigned a0, unsigned a1, unsigned a2, unsigned a3,
        unsigned b0, unsigned b1) {
    asm volatile(
        "mma.sync.aligned.m16n8k16.row.col.f32.bf16.bf16.f32 "
        "{%0,%1,%2,%3},{%4,%5,%6,%7},{%8,%9},{%0,%1,%2,%3};\n"
        : "+f"(c[0]), "+f"(c[1]), "+f"(c[2]), "+f"(c[3])
        : "r"(a0), "r"(a1), "r"(a2), "r"(a3), "r"(b0), "r"(b1));
}

// ---------------- K0: fp32 -> bf16 pack ----------------
__global__ void convert_kernel(const float* __restrict__ x,
                               const float* __restrict__ wq, const float* __restrict__ wk,
                               const float* __restrict__ wv, const float* __restrict__ wo) {
    int stride = gridDim.x * blockDim.x;
    int t0 = blockIdx.x * blockDim.x + threadIdx.x;
    for (int i = t0; i < NB*CCH*SSP; i += stride) g_xb[i] = f2bf(x[i]);
    const int WSZ = CCH*CCH;
    for (int i = t0; i < WSZ; i += stride) {
        g_W[i]         = f2bf(wq[i]);
        g_W[WSZ + i]   = f2bf(wk[i]);
        g_W[2*WSZ + i] = f2bf(wv[i]);
        g_W[3*WSZ + i] = f2bf(wo[i]);
    }
}

// ---------------- K1/K3: tiled GEMM  Out[o,s] = W[o,:] @ B[:,s] + bias ----------------
// phase 0: blockIdx.z = which*2 + n (which: 0=Q,1=K,2=V), 768 CTAs. phase 1: z=n, 256 CTAs.
// Tile 128x128, K-slab 64, 3-stage cp.async, one sync per slab.
#define GSTAGE 33792
#define G_SMEM (3*GSTAGE)
__global__ __launch_bounds__(256,2) void gemm_kernel(int phase,
        const float* __restrict__ bq, const float* __restrict__ bk,
        const float* __restrict__ bv, const float* __restrict__ bo,
        const float* __restrict__ x, const float* __restrict__ gamma,
        float* __restrict__ out) {
    extern __shared__ __align__(1024) unsigned char gsm[];
    unsigned smb = smem_u32(gsm);

    int which, n;
    const unsigned short* Bm;
    if (phase == 0) {
        int z = blockIdx.z; which = z >> 1; n = z & 1;
        Bm = g_xb + n * (CCH * SSP);
    } else {
        which = 3; n = blockIdx.z;
        Bm = g_Oc + n * (CCH * SSP);
    }
    const unsigned short* Wm = g_W + which * (CCH * CCH);

    int tid = threadIdx.x;
    int mBase = blockIdx.y * 128, sBase = blockIdx.x * 128;
    int warp = tid >> 5, lane = tid & 31, g = lane >> 2, qi = lane & 3;
    int wm = warp >> 1, wn = warp & 1;
    int lq = (lane & 7) + 8*((lane >> 3) & 1);
    int lc = 8*(lane >> 4);

    auto swA = [](int r, int k) -> unsigned {
        return (unsigned)(r*128 + ((2*k) ^ ((r & 7) << 4)));
    };

    float acc[2][8][4];
    #pragma unroll
    for (int a = 0; a < 2; a++)
        #pragma unroll
        for (int b = 0; b < 8; b++)
            #pragma unroll
            for (int c = 0; c < 4; c++) acc[a][b][c] = 0.f;

    auto stage = [&](int s) {
        unsigned ab = smb + (unsigned)(s % 3) * (unsigned)GSTAGE;
        unsigned bb = ab + 16384u;
        int kc = s * 64;
        #pragma unroll
        for (int j = 0; j < 4; j++) {
            int u = tid + j*256;
            int ar = u >> 3, ak = (u & 7) * 8;
            cpasync16(ab + swA(ar, ak), &Wm[(size_t)(mBase + ar)*CCH + kc + ak]);
            int br = u >> 4, bc = (u & 15) * 8;
            cpasync16(bb + (unsigned)(br*136 + bc)*2u, &Bm[(size_t)(kc + br)*SSP + sBase + bc]);
        }
        cpcommit();
    };

    stage(0);
    stage(1);

    for (int s = 0; s < 8; s++) {
        if (s < 7) cpwait<1>(); else cpwait<0>();
        __syncthreads();
        if (s + 2 < 8) stage(s + 2);

        unsigned ab = smb + (unsigned)(s % 3) * (unsigned)GSTAGE;
        unsigned bb = ab + 16384u;
        #pragma unroll
        for (int ks = 0; ks < 4; ks++) {
            int k0 = ks * 16;
            unsigned af[2][4], bf[8][2];
            #pragma unroll
            for (int mt = 0; mt < 2; mt++)
                ldsm_x4(af[mt][0], af[mt][1], af[mt][2], af[mt][3],
                        ab + swA(wm*32 + mt*16 + lq, k0 + lc));
            #pragma unroll
            for (int ng = 0; ng < 4; ng++) {
                unsigned r0, r1, r2, r3;
                ldsm_x4_t(r0, r1, r2, r3,
                        bb + (unsigned)((k0 + lq)*136 + wn*64 + ng*16 + lc)*2u);
                bf[2*ng][0] = r0;  bf[2*ng][1] = r1;
                bf[2*ng+1][0] = r2; bf[2*ng+1][1] = r3;
            }
            #pragma unroll
            for (int mt = 0; mt < 2; mt++)
                #pragma unroll
                for (int nt = 0; nt < 8; nt++)
                    mma16816(acc[mt][nt], af[mt][0], af[mt][1], af[mt][2], af[mt][3],
                             bf[nt][0], bf[nt][1]);
        }
    }

    // ---------------- epilogue ----------------
    if (which <= 1) {
        // Q/K: smem-transpose epilogue into stage-0 buffer, coalesced 16B stores.
        const float* bias = (which == 0) ? bq : bk;
        unsigned short* dst = (which == 0) ? g_Qt : g_Kt;
        float qs = (which == 0) ? QSCALE : 1.0f;
        float bA0 = bias[mBase + wm*32 + g];
        float bA1 = bias[mBase + wm*32 + g + 8];
        float bB0 = bias[mBase + wm*32 + 16 + g];
        float bB1 = bias[mBase + wm*32 + 16 + g + 8];
        #pragma unroll
        for (int p = 0; p < 2; p++) {
            if (wn == p) {
                #pragma unroll
                for (int mt = 0; mt < 2; mt++) {
                    int r0 = wm*32 + mt*16 + g, r1 = r0 + 8;
                    float b0 = mt ? bB0 : bA0;
                    float b1 = mt ? bB1 : bA1;
                    #pragma unroll
                    for (int nt = 0; nt < 8; nt++) {
                        int sl = nt*8 + 2*qi;
                        sts16(smb + (unsigned)( sl     *136 + r0)*2u, f2bf((acc[mt][nt][0] + b0)*qs));
                        sts16(smb + (unsigned)((sl + 1)*136 + r0)*2u, f2bf((acc[mt][nt][1] + b0)*qs));
                        sts16(smb + (unsigned)( sl     *136 + r1)*2u, f2bf((acc[mt][nt][2] + b1)*qs));
                        sts16(smb + (unsigned)((sl + 1)*136 + r1)*2u, f2bf((acc[mt][nt][3] + b1)*qs));
                    }
                }
            }
            __syncthreads();
            #pragma unroll
            for (int r = 0; r < 4; r++) {
                int u = tid + r*256;
                int row = u >> 4, c = (u & 15) * 8;
                int h = (mBase + c) >> 6;
                int d = (mBase + c) & 63;
                int srow = sBase + p*64 + row;
                uint4 v = *(const uint4*)(gsm + (unsigned)(row*136 + c)*2u);
                *(uint4*)&dst[((size_t)(n*8 + h)*SSP + srow)*HD + d] = v;
            }
            __syncthreads();
        }
    } else if (which == 2) {
        // V: channel-major pair stores
        #pragma unroll
        for (int mt = 0; mt < 2; mt++) {
            int o0 = mBase + wm*32 + mt*16 + g;
            int o1 = o0 + 8;
            float b0 = bv[o0], b1 = bv[o1];
            #pragma unroll
            for (int nt = 0; nt < 8; nt++) {
                int s = sBase + wn*64 + nt*8 + 2*qi;
                unsigned short* d0p = g_Vc + (n*CCH + o0) * SSP;
                unsigned short* d1p = g_Vc + (n*CCH + o1) * SSP;
                *(unsigned*)&d0p[s] = pk2(acc[mt][nt][0] + b0, acc[mt][nt][1] + b0);
                *(unsigned*)&d1p[s] = pk2(acc[mt][nt][2] + b1, acc[mt][nt][3] + b1);
            }
        }
    } else {
        // O: fp32 residual output
        float gm = gamma[0];
        #pragma unroll
        for (int mt = 0; mt < 2; mt++) {
            int o0 = mBase + wm*32 + mt*16 + g;
            int o1 = o0 + 8;
            float b0 = bo[o0], b1 = bo[o1];
            #pragma unroll
            for (int nt = 0; nt < 8; nt++) {
                int s = sBase + wn*64 + nt*8 + 2*qi;
                int i0 = (n*CCH + o0) * SSP + s;
                int i1 = (n*CCH + o1) * SSP + s;
                out[i0]     = gm * (acc[mt][nt][0] + b0) + x[i0];
                out[i0 + 1] = gm * (acc[mt][nt][1] + b0) + x[i0 + 1];
                out[i1]     = gm * (acc[mt][nt][2] + b1) + x[i1];
                out[i1 + 1] = gm * (acc[mt][nt][3] + b1) + x[i1 + 1];
            }
        }
    }
}

// ---------------- K2: flash attention, Br=128, Bc=128/stage (2x64 halves) ----------------
// 512 CTAs. Q pre-scaled (log2 units); no running max; row sums via ones-MMA.
// 3-stage cp.async pipeline (stage = K 16K + V 16K), ONE sync per 128 columns.
#define FL_SMEM (16384 + 3*32768)
__global__ __launch_bounds__(256,2) void flash_kernel() {
    extern __shared__ __align__(1024) unsigned char smarr[];
    unsigned qb = smem_u32(smarr);
    unsigned kv = qb + 16384;   // stage s at kv + (s%3)*32768: [K0 8K | K1 8K | V0 8K | V1 8K]

    int tid = threadIdx.x;
    int nh = blockIdx.y;            // n*8 + h
    int s0 = blockIdx.x * 128;
    const unsigned short* Qg = g_Qt + (size_t)nh * (SSP*HD);
    const unsigned short* Kg = g_Kt + (size_t)nh * (SSP*HD);
    const unsigned short* Vg = g_Vc + (size_t)nh * (HD*SSP);

    int warp = tid >> 5, lane = tid & 31, g = lane >> 2, qi = lane & 3;
    int mrow = warp * 16;
    int lq  = (lane & 7) + 8*((lane >> 3) & 1);
    int lc  = 8*(lane >> 4);
    int lq2 = (lane & 7) + 8*(lane >> 4);
    int lc2 = 8*((lane >> 3) & 1);

    auto sw = [](int row, int ch) -> unsigned {
        return (unsigned)(row*128 + ((ch*2) ^ ((row & 7) << 4)));
    };

    // stage loader: 128 t-columns (two 64-wide halves of K and V)
    auto stageld = [&](int s) {
        unsigned sb = kv + (unsigned)(s % 3) * 32768u;
        int t0 = s * 128;
        #pragma unroll
        for (int r = 0; r < 2; r++) {
            int u = tid + r*256; int row = u >> 3, c = (u & 7) * 8;
            cpasync16(sb +          sw(row, c), &Kg[(size_t)(t0 + row)*HD + c]);
            cpasync16(sb + 8192u  + sw(row, c), &Kg[(size_t)(t0 + 64 + row)*HD + c]);
            cpasync16(sb + 16384u + sw(row, c), &Vg[(size_t)row*SSP + t0 + c]);
            cpasync16(sb + 24576u + sw(row, c), &Vg[(size_t)row*SSP + t0 + 64 + c]);
        }
        cpcommit();
    };

    // prologue: Q + stage0 in group 0, stage1 in group 1
    #pragma unroll
    for (int r = 0; r < 4; r++) {
        int u = tid + r*256; int row = u >> 3, c = (u & 7) * 8;
        cpasync16(qb + sw(row, c), &Qg[(size_t)(s0 + row)*HD + c]);
    }
    stageld(0);
    stageld(1);

    float lsum[4];
    lsum[0] = lsum[1] = lsum[2] = lsum[3] = 0.f;
    float o[8][4];
    #pragma unroll
    for (int a = 0; a < 8; a++)
        #pragma unroll
        for (int b = 0; b < 4; b++) o[a][b] = 0.f;

    for (int it = 0; it < 32; it++) {
        unsigned sb = kv + (unsigned)(((unsigned)it) % 3u) * 32768u;
        if (it < 31) cpwait<1>(); else cpwait<0>();
        __syncthreads();
        if (it + 2 < 32) stageld(it + 2);

        #pragma unroll
        for (int hlf = 0; hlf < 2; hlf++) {
            unsigned kb = sb + (unsigned)hlf * 8192u;
            unsigned vb = sb + 16384u + (unsigned)hlf * 8192u;

            // S = Q @ K^T (log2 units)
            float sc[8][4];
            #pragma unroll
            for (int a = 0; a < 8; a++)
                #pragma unroll
                for (int b = 0; b < 4; b++) sc[a][b] = 0.f;
            #pragma unroll
            for (int kk = 0; kk < 4; kk++) {
                int k0 = kk * 16;
                unsigned a0, a1, a2, a3;
                ldsm_x4(a0, a1, a2, a3, qb + sw(mrow + lq, k0 + lc));
                #pragma unroll
                for (int ng = 0; ng < 4; ng++) {
                    unsigned r0, r1, r2, r3;
                    ldsm_x4(r0, r1, r2, r3, kb + sw(ng*16 + lq2, k0 + lc2));
                    mma16816(sc[2*ng],     a0, a1, a2, a3, r0, r1);
                    mma16816(sc[2*ng + 1], a0, a1, a2, a3, r2, r3);
                }
            }

            // p = 2^s
            #pragma unroll
            for (int nt = 0; nt < 8; nt++) {
                sc[nt][0] = ex2(sc[nt][0]);
                sc[nt][1] = ex2(sc[nt][1]);
                sc[nt][2] = ex2(sc[nt][2]);
                sc[nt][3] = ex2(sc[nt][3]);
            }

            // O += P @ V ; row sums via ones-MMA (no scalar adds, no shuffles)
            #pragma unroll
            for (int kt = 0; kt < 4; kt++) {
                unsigned a0 = pk2(sc[2*kt    ][0], sc[2*kt    ][1]);
                unsigned a1 = pk2(sc[2*kt    ][2], sc[2*kt    ][3]);
                unsigned a2 = pk2(sc[2*kt + 1][0], sc[2*kt + 1][1]);
                unsigned a3 = pk2(sc[2*kt + 1][2], sc[2*kt + 1][3]);
                mma16816(lsum, a0, a1, a2, a3, ONES2, ONES2);
                #pragma unroll
                for (int ng = 0; ng < 4; ng++) {
                    unsigned r0, r1, r2, r3;
                    ldsm_x4(r0, r1, r2, r3, vb + sw(ng*16 + lq2, kt*16 + lc2));
                    mma16816(o[2*ng],     a0, a1, a2, a3, r0, r1);
                    mma16816(o[2*ng + 1], a0, a1, a2, a3, r2, r3);
                }
            }
        }
    }

    // every lane holds its two row sums directly
    float inv0 = 1.f / lsum[0], inv1 = 1.f / lsum[2];

    // finalize + transpose via smem, write channel-major bf16
    __syncthreads();
    unsigned short* Os = (unsigned short*)smarr;   // 64*136 halves = 17408 B
    #pragma unroll
    for (int nt = 0; nt < 8; nt++) {
        int dv = nt*8 + 2*qi;
        Os[ dv     *136 + mrow + g    ] = f2bf(o[nt][0] * inv0);
        Os[(dv + 1)*136 + mrow + g    ] = f2bf(o[nt][1] * inv0);
        Os[ dv     *136 + mrow + g + 8] = f2bf(o[nt][2] * inv1);
        Os[(dv + 1)*136 + mrow + g + 8] = f2bf(o[nt][3] * inv1);
    }
    __syncthreads();
    unsigned short* Og = g_Oc + (size_t)nh * (HD*SSP) + s0;
    #pragma unroll
    for (int r = 0; r < 16; r++) {
        int u = tid + r*256; int dv = u >> 6, swc = u & 63;
        *(unsigned*)&Og[(size_t)dv*SSP + swc*2] = *(const unsigned*)&Os[dv*136 + swc*2];
    }
}

// ---------------- launch ----------------
extern "C" void kernel_launch(void* const* d_in, const int* in_sizes, int n_in,
                              void* d_out, int out_size) {
    const float* x     = (const float*)d_in[0];
    const float* Wq    = (const float*)d_in[1];
    const float* bq    = (const float*)d_in[2];
    const float* Wk    = (const float*)d_in[3];
    const float* bk    = (const float*)d_in[4];
    const float* Wv    = (const float*)d_in[5];
    const float* bv    = (const float*)d_in[6];
    const float* Wo    = (const float*)d_in[7];
    const float* bo    = (const float*)d_in[8];
    const float* gamma = (const float*)d_in[9];
    float* out = (float*)d_out;

    cudaFuncSetAttribute(flash_kernel,
        cudaFuncAttributeMaxDynamicSharedMemorySize, FL_SMEM);
    cudaFuncSetAttribute(gemm_kernel,
        cudaFuncAttributeMaxDynamicSharedMemorySize, G_SMEM);

    convert_kernel<<<1024, 256>>>(x, Wq, Wk, Wv, Wo);
    gemm_kernel<<<dim3(SSP/128, CCH/128, 6), 256, G_SMEM>>>(0, bq, bk, bv, bo, x, gamma, out);
    flash_kernel<<<dim3(SSP/128, NHTOT), 256, FL_SMEM>>>();
    gemm_kernel<<<dim3(SSP/128, CCH/128, NB), 256, G_SMEM>>>(1, bq, bk, bv, bo, x, gamma, out);
}

// round 11
// speedup vs baseline: 1.0903x; 1.0002x over previous
#include <cuda_runtime.h>
#include <cuda_bf16.h>

// Problem constants
#define NB    2
#define CCH   512
#define SSP   4096     // 64*64 spatial tokens
#define NH    8
#define HD    64
#define NHTOT (NB*NH)  // 16

// Q pre-scale: 1/sqrt(64) * log2(e)  (scores come out in log2 units)
#define QSCALE 0.18033688011f
// bf16 1.0 pair (ones B-fragment for row-sum MMA)
#define ONES2  0x3F803F80u

// ---------------- scratch (static __device__, no allocations) ----------------
__device__ __align__(16) unsigned short g_xT[NB*SSP*CCH];   // x^T bf16, token-major [n][s][c]
__device__ __align__(16) unsigned short g_W [4*CCH*CCH];    // Wq,Wk,Wv,Wo bf16 [o][c]
__device__ __align__(16) unsigned short g_Qt[NHTOT*SSP*HD]; // [n*8+h][s][d] (pre-scaled)
__device__ __align__(16) unsigned short g_Kt[NHTOT*SSP*HD]; // [n*8+h][s][d]
__device__ __align__(16) unsigned short g_Vc[NB*CCH*SSP];   // [n][c][s] (c = h*64+d)
__device__ __align__(16) unsigned short g_Ot[NB*SSP*CCH];   // attn out token-major [n][s][c]

// ---------------- helpers ----------------
__device__ __forceinline__ unsigned short f2bf(float v) {
    __nv_bfloat16 h = __float2bfloat16(v);
    return *reinterpret_cast<unsigned short*>(&h);
}
__device__ __forceinline__ unsigned pk2(float a, float b) {
    __nv_bfloat162 t = __floats2bfloat162_rn(a, b);
    return *reinterpret_cast<unsigned*>(&t);
}
__device__ __forceinline__ float ex2(float x) {
    float y;
    asm("ex2.approx.ftz.f32 %0, %1;" : "=f"(y) : "f"(x));
    return y;
}
__device__ __forceinline__ unsigned smem_u32(const void* p) {
    return (unsigned)__cvta_generic_to_shared(p);
}
__device__ __forceinline__ void cpasync16(unsigned dst, const void* src) {
    asm volatile("cp.async.cg.shared.global [%0], [%1], 16;\n" :: "r"(dst), "l"(src));
}
__device__ __forceinline__ void cpcommit() {
    asm volatile("cp.async.commit_group;\n" ::: "memory");
}
template<int N> __device__ __forceinline__ void cpwait() {
    asm volatile("cp.async.wait_group %0;\n" :: "n"(N) : "memory");
}
__device__ __forceinline__ void ldsm_x4(unsigned& r0, unsigned& r1, unsigned& r2,
                                        unsigned& r3, unsigned addr) {
    asm volatile("ldmatrix.sync.aligned.m8n8.x4.shared.b16 {%0,%1,%2,%3}, [%4];"
        : "=r"(r0), "=r"(r1), "=r"(r2), "=r"(r3) : "r"(addr));
}
// D += A*B, m16n8k16 bf16 -> f32
__device__ __forceinline__ void mma16816(float* c,
        unsigned a0, unsigned a1, unsigned a2, unsigned a3,
        unsigned b0, unsigned b1) {
    asm volatile(
        "mma.sync.aligned.m16n8k16.row.col.f32.bf16.bf16.f32 "
        "{%0,%1,%2,%3},{%4,%5,%6,%7},{%8,%9},{%0,%1,%2,%3};\n"
        : "+f"(c[0]), "+f"(c[1]), "+f"(c[2]), "+f"(c[3])
        : "r"(a0), "r"(a1), "r"(a2), "r"(a3), "r"(b0), "r"(b1));
}

// ---------------- K0a: weights fp32 -> bf16 ----------------
__global__ void convw_kernel(const float* __restrict__ wq, const float* __restrict__ wk,
                             const float* __restrict__ wv, const float* __restrict__ wo) {
    int stride = gridDim.x * blockDim.x;
    int t0 = blockIdx.x * blockDim.x + threadIdx.x;
    const int WSZ = CCH*CCH;
    for (int i = t0; i < WSZ; i += stride) {
        g_W[i]         = f2bf(wq[i]);
        g_W[WSZ + i]   = f2bf(wk[i]);
        g_W[2*WSZ + i] = f2bf(wv[i]);
        g_W[3*WSZ + i] = f2bf(wo[i]);
    }
}

// ---------------- K0b: x [n][c][s] fp32 -> x^T [n][s][c] bf16 ----------------
__global__ void transpose_kernel(const float* __restrict__ x) {
    __shared__ float t[32][33];
    int n = blockIdx.z;
    int s0 = blockIdx.x * 32, c0 = blockIdx.y * 32;
    int tx = threadIdx.x, ty = threadIdx.y;   // 32 x 8
    const float* src = x + ((size_t)n*CCH + c0)*SSP + s0;
    #pragma unroll
    for (int k = 0; k < 4; k++)
        t[ty + 8*k][tx] = src[(size_t)(ty + 8*k)*SSP + tx];
    __syncthreads();
    unsigned short* dst = g_xT + ((size_t)n*SSP + s0)*CCH + c0;
    #pragma unroll
    for (int k = 0; k < 4; k++)
        dst[(size_t)(ty + 8*k)*CCH + tx] = f2bf(t[tx][ty + 8*k]);
}

// ---------------- K1/K3: tiled GEMM, all operands K-major (stride-512 rows) ----------------
// phase 0, z = which*2+n (0=Q,1=K,2=V); phase 1: z=n, which=3.
// Q/K: m=s (A=xT), n=d_out (B=W)   -> acc [s][d], direct stores to g_Qt/g_Kt.
// V:   m=c (A=Wv), n=s (B=xT)      -> g_Vc channel-major.
// O:   m=c (A=Wo), n=s (B=Ot)      -> fp32 out + residual.
// Tile 128x128, K-slab 64, 3-stage cp.async, one sync per slab, non-trans ldsm only.
#define GSTAGE 32768
#define G_SMEM (3*GSTAGE)
__global__ __launch_bounds__(256,2) void gemm_kernel(int phase,
        const float* __restrict__ bq, const float* __restrict__ bk,
        const float* __restrict__ bv, const float* __restrict__ bo,
        const float* __restrict__ x, const float* __restrict__ gamma,
        float* __restrict__ out) {
    extern __shared__ __align__(1024) unsigned char gsm[];
    unsigned smb = smem_u32(gsm);

    int which, n;
    if (phase == 0) { int z = blockIdx.z; which = z >> 1; n = z & 1; }
    else            { which = 3; n = blockIdx.z; }

    int tid = threadIdx.x;
    int sBase = blockIdx.x * 128;   // token-tile
    int oBase = blockIdx.y * 128;   // output-channel tile
    const unsigned short* xTn = g_xT + (size_t)n * SSP * CCH;
    const unsigned short* Am;
    const unsigned short* Bm;
    if (which <= 1) {
        Am = xTn + (size_t)sBase*CCH;
        Bm = g_W + (size_t)which*CCH*CCH + (size_t)oBase*CCH;
    } else if (which == 2) {
        Am = g_W + 2*(size_t)CCH*CCH + (size_t)oBase*CCH;
        Bm = xTn + (size_t)sBase*CCH;
    } else {
        Am = g_W + 3*(size_t)CCH*CCH + (size_t)oBase*CCH;
        Bm = g_Ot + (size_t)n*SSP*CCH + (size_t)sBase*CCH;
    }

    int warp = tid >> 5, lane = tid & 31, g = lane >> 2, qi = lane & 3;
    int wm = warp >> 1, wn = warp & 1;
    int lq  = (lane & 7) + 8*((lane >> 3) & 1);  // A-operand ldsm row
    int lc  = 8*(lane >> 4);
    int lq2 = (lane & 7) + 8*(lane >> 4);        // B-operand ldsm row
    int lc2 = 8*((lane >> 3) & 1);

    auto sw = [](int r, int k) -> unsigned {
        return (unsigned)(r*128 + ((2*k) ^ ((r & 7) << 4)));
    };

    float acc[2][8][4];
    #pragma unroll
    for (int a = 0; a < 2; a++)
        #pragma unroll
        for (int b = 0; b < 8; b++)
            #pragma unroll
            for (int c = 0; c < 4; c++) acc[a][b][c] = 0.f;

    auto stage = [&](int s) {
        unsigned ab = smb + (unsigned)(s % 3) * (unsigned)GSTAGE;
        unsigned bb = ab + 16384u;
        int kc = s * 64;
        #pragma unroll
        for (int j = 0; j < 4; j++) {
            int u = tid + j*256;
            int r = u >> 3, ck = (u & 7) * 8;
            cpasync16(ab + sw(r, ck), &Am[(size_t)r*CCH + kc + ck]);
            cpasync16(bb + sw(r, ck), &Bm[(size_t)r*CCH + kc + ck]);
        }
        cpcommit();
    };

    stage(0);
    stage(1);

    for (int s = 0; s < 8; s++) {
        if (s < 7) cpwait<1>(); else cpwait<0>();
        __syncthreads();
        if (s + 2 < 8) stage(s + 2);

        unsigned ab = smb + (unsigned)(s % 3) * (unsigned)GSTAGE;
        unsigned bb = ab + 16384u;
        #pragma unroll
        for (int ks = 0; ks < 4; ks++) {
            int k0 = ks * 16;
            unsigned af[2][4], bf[8][2];
            #pragma unroll
            for (int mt = 0; mt < 2; mt++)
                ldsm_x4(af[mt][0], af[mt][1], af[mt][2], af[mt][3],
                        ab + sw(wm*32 + mt*16 + lq, k0 + lc));
            #pragma unroll
            for (int ng = 0; ng < 4; ng++) {
                unsigned r0, r1, r2, r3;
                ldsm_x4(r0, r1, r2, r3,
                        bb + sw(wn*64 + ng*16 + lq2, k0 + lc2));
                bf[2*ng][0] = r0;  bf[2*ng][1] = r1;
                bf[2*ng+1][0] = r2; bf[2*ng+1][1] = r3;
            }
            #pragma unroll
            for (int mt = 0; mt < 2; mt++)
                #pragma unroll
                for (int nt = 0; nt < 8; nt++)
                    mma16816(acc[mt][nt], af[mt][0], af[mt][1], af[mt][2], af[mt][3],
                             bf[nt][0], bf[nt][1]);
        }
    }

    // ---------------- epilogue (no smem reuse, no barriers) ----------------
    if (which <= 1) {
        // acc rows = tokens, cols = output channels -> direct [s][d] stores
        const float* bias = (which == 0) ? bq : bk;
        unsigned short* dst = (which == 0) ? g_Qt : g_Kt;
        float qs = (which == 0) ? QSCALE : 1.0f;
        #pragma unroll
        for (int nt = 0; nt < 8; nt++) {
            int c = oBase + wn*64 + nt*8 + 2*qi;
            float b0 = bias[c], b1 = bias[c + 1];
            int h = c >> 6, d = c & 63;
            unsigned short* dh = dst + (size_t)(n*8 + h)*(SSP*HD) + d;
            #pragma unroll
            for (int mt = 0; mt < 2; mt++) {
                int r0 = sBase + wm*32 + mt*16 + g;
                *(unsigned*)&dh[(size_t) r0      *HD] =
                    pk2((acc[mt][nt][0] + b0)*qs, (acc[mt][nt][1] + b1)*qs);
                *(unsigned*)&dh[(size_t)(r0 + 8) *HD] =
                    pk2((acc[mt][nt][2] + b0)*qs, (acc[mt][nt][3] + b1)*qs);
            }
        }
    } else if (which == 2) {
        // V: channel-major pair stores
        #pragma unroll
        for (int mt = 0; mt < 2; mt++) {
            int o0 = oBase + wm*32 + mt*16 + g;
            int o1 = o0 + 8;
            float b0 = bv[o0], b1 = bv[o1];
            #pragma unroll
            for (int nt = 0; nt < 8; nt++) {
                int s = sBase + wn*64 + nt*8 + 2*qi;
                unsigned short* d0p = g_Vc + ((size_t)n*CCH + o0) * SSP;
                unsigned short* d1p = g_Vc + ((size_t)n*CCH + o1) * SSP;
                *(unsigned*)&d0p[s] = pk2(acc[mt][nt][0] + b0, acc[mt][nt][1] + b0);
                *(unsigned*)&d1p[s] = pk2(acc[mt][nt][2] + b1, acc[mt][nt][3] + b1);
            }
        }
    } else {
        // O: fp32 residual output (out is [n][c][s] like x)
        float gm = gamma[0];
        #pragma unroll
        for (int mt = 0; mt < 2; mt++) {
            int o0 = oBase + wm*32 + mt*16 + g;
            int o1 = o0 + 8;
            float b0 = bo[o0], b1 = bo[o1];
            #pragma unroll
            for (int nt = 0; nt < 8; nt++) {
                int s = sBase + wn*64 + nt*8 + 2*qi;
                size_t i0 = ((size_t)n*CCH + o0) * SSP + s;
                size_t i1 = ((size_t)n*CCH + o1) * SSP + s;
                out[i0]     = gm * (acc[mt][nt][0] + b0) + x[i0];
                out[i0 + 1] = gm * (acc[mt][nt][1] + b0) + x[i0 + 1];
                out[i1]     = gm * (acc[mt][nt][2] + b1) + x[i1];
                out[i1 + 1] = gm * (acc[mt][nt][3] + b1) + x[i1 + 1];
            }
        }
    }
}

// ---------------- K2: flash attention, Br=128, Bc=128/stage ----------------
// 512 CTAs. Q pre-scaled (log2 units); no running max; row sums via ones-MMA.
// Writes O token-major [n][s][c] directly from fragments (no transpose epilogue).
#define FL_SMEM (16384 + 3*32768)
__global__ __launch_bounds__(256,2) void flash_kernel() {
    extern __shared__ __align__(1024) unsigned char smarr[];
    unsigned qb = smem_u32(smarr);
    unsigned kv = qb + 16384;   // stage s at kv + (s%3)*32768: [K0 8K | K1 8K | V0 8K | V1 8K]

    int tid = threadIdx.x;
    int nh = blockIdx.y;            // n*8 + h
    int s0 = blockIdx.x * 128;
    const unsigned short* Qg = g_Qt + (size_t)nh * (SSP*HD);
    const unsigned short* Kg = g_Kt + (size_t)nh * (SSP*HD);
    const unsigned short* Vg = g_Vc + (size_t)nh * (HD*SSP);

    int warp = tid >> 5, lane = tid & 31, g = lane >> 2, qi = lane & 3;
    int mrow = warp * 16;
    int lq  = (lane & 7) + 8*((lane >> 3) & 1);
    int lc  = 8*(lane >> 4);
    int lq2 = (lane & 7) + 8*(lane >> 4);
    int lc2 = 8*((lane >> 3) & 1);

    auto sw = [](int row, int ch) -> unsigned {
        return (unsigned)(row*128 + ((ch*2) ^ ((row & 7) << 4)));
    };

    auto stageld = [&](int s) {
        unsigned sb = kv + (unsigned)(s % 3) * 32768u;
        int t0 = s * 128;
        #pragma unroll
        for (int r = 0; r < 2; r++) {
            int u = tid + r*256; int row = u >> 3, c = (u & 7) * 8;
            cpasync16(sb +          sw(row, c), &Kg[(size_t)(t0 + row)*HD + c]);
            cpasync16(sb + 8192u  + sw(row, c), &Kg[(size_t)(t0 + 64 + row)*HD + c]);
            cpasync16(sb + 16384u + sw(row, c), &Vg[(size_t)row*SSP + t0 + c]);
            cpasync16(sb + 24576u + sw(row, c), &Vg[(size_t)row*SSP + t0 + 64 + c]);
        }
        cpcommit();
    };

    // prologue: Q + stage0 in group 0, stage1 in group 1
    #pragma unroll
    for (int r = 0; r < 4; r++) {
        int u = tid + r*256; int row = u >> 3, c = (u & 7) * 8;
        cpasync16(qb + sw(row, c), &Qg[(size_t)(s0 + row)*HD + c]);
    }
    stageld(0);
    stageld(1);

    float lsum[4];
    lsum[0] = lsum[1] = lsum[2] = lsum[3] = 0.f;
    float o[8][4];
    #pragma unroll
    for (int a = 0; a < 8; a++)
        #pragma unroll
        for (int b = 0; b < 4; b++) o[a][b] = 0.f;

    for (int it = 0; it < 32; it++) {
        unsigned sb = kv + (unsigned)(((unsigned)it) % 3u) * 32768u;
        if (it < 31) cpwait<1>(); else cpwait<0>();
        __syncthreads();
        if (it + 2 < 32) stageld(it + 2);

        #pragma unroll
        for (int hlf = 0; hlf < 2; hlf++) {
            unsigned kb = sb + (unsigned)hlf * 8192u;
            unsigned vb = sb + 16384u + (unsigned)hlf * 8192u;

            // S = Q @ K^T (log2 units)
            float sc[8][4];
            #pragma unroll
            for (int a = 0; a < 8; a++)
                #pragma unroll
                for (int b = 0; b < 4; b++) sc[a][b] = 0.f;
            #pragma unroll
            for (int kk = 0; kk < 4; kk++) {
                int k0 = kk * 16;
                unsigned a0, a1, a2, a3;
                ldsm_x4(a0, a1, a2, a3, qb + sw(mrow + lq, k0 + lc));
                #pragma unroll
                for (int ng = 0; ng < 4; ng++) {
                    unsigned r0, r1, r2, r3;
                    ldsm_x4(r0, r1, r2, r3, kb + sw(ng*16 + lq2, k0 + lc2));
                    mma16816(sc[2*ng],     a0, a1, a2, a3, r0, r1);
                    mma16816(sc[2*ng + 1], a0, a1, a2, a3, r2, r3);
                }
            }

            // p = 2^s
            #pragma unroll
            for (int nt = 0; nt < 8; nt++) {
                sc[nt][0] = ex2(sc[nt][0]);
                sc[nt][1] = ex2(sc[nt][1]);
                sc[nt][2] = ex2(sc[nt][2]);
                sc[nt][3] = ex2(sc[nt][3]);
            }

            // O += P @ V ; row sums via ones-MMA
            #pragma unroll
            for (int kt = 0; kt < 4; kt++) {
                unsigned a0 = pk2(sc[2*kt    ][0], sc[2*kt    ][1]);
                unsigned a1 = pk2(sc[2*kt    ][2], sc[2*kt    ][3]);
                unsigned a2 = pk2(sc[2*kt + 1][0], sc[2*kt + 1][1]);
                unsigned a3 = pk2(sc[2*kt + 1][2], sc[2*kt + 1][3]);
                mma16816(lsum, a0, a1, a2, a3, ONES2, ONES2);
                #pragma unroll
                for (int ng = 0; ng < 4; ng++) {
                    unsigned r0, r1, r2, r3;
                    ldsm_x4(r0, r1, r2, r3, vb + sw(ng*16 + lq2, kt*16 + lc2));
                    mma16816(o[2*ng],     a0, a1, a2, a3, r0, r1);
                    mma16816(o[2*ng + 1], a0, a1, a2, a3, r2, r3);
                }
            }
        }
    }

    // every lane holds its two row sums directly
    float inv0 = 1.f / lsum[0], inv1 = 1.f / lsum[2];

    // finalize: direct token-major stores [n][s][c] (no transpose)
    int nn = nh >> 3, h = nh & 7;
    unsigned short* Og = g_Ot + ((size_t)nn*SSP + s0)*CCH + h*64;
    int r0w = mrow + g, r1w = mrow + g + 8;
    #pragma unroll
    for (int nt = 0; nt < 8; nt++) {
        int dv = nt*8 + 2*qi;
        *(unsigned*)&Og[(size_t)r0w*CCH + dv] = pk2(o[nt][0]*inv0, o[nt][1]*inv0);
        *(unsigned*)&Og[(size_t)r1w*CCH + dv] = pk2(o[nt][2]*inv1, o[nt][3]*inv1);
    }
}

// ---------------- launch ----------------
extern "C" void kernel_launch(void* const* d_in, const int* in_sizes, int n_in,
                              void* d_out, int out_size) {
    const float* x     = (const float*)d_in[0];
    const float* Wq    = (const float*)d_in[1];
    const float* bq    = (const float*)d_in[2];
    const float* Wk    = (const float*)d_in[3];
    const float* bk    = (const float*)d_in[4];
    const float* Wv    = (const float*)d_in[5];
    const float* bv    = (const float*)d_in[6];
    const float* Wo    = (const float*)d_in[7];
    const float* bo    = (const float*)d_in[8];
    const float* gamma = (const float*)d_in[9];
    float* out = (float*)d_out;

    cudaFuncSetAttribute(flash_kernel,
        cudaFuncAttributeMaxDynamicSharedMemorySize, FL_SMEM);
    cudaFuncSetAttribute(gemm_kernel,
        cudaFuncAttributeMaxDynamicSharedMemorySize, G_SMEM);

    convw_kernel<<<512, 256>>>(Wq, Wk, Wv, Wo);
    transpose_kernel<<<dim3(SSP/32, CCH/32, NB), dim3(32, 8)>>>(x);
    gemm_kernel<<<dim3(SSP/128, CCH/128, 6), 256, G_SMEM>>>(0, bq, bk, bv, bo, x, gamma, out);
    flash_kernel<<<dim3(SSP/128, NHTOT), 256, FL_SMEM>>>();
    gemm_kernel<<<dim3(SSP/128, CCH/128, NB), 256, G_SMEM>>>(1, bq, bk, bv, bo, x, gamma, out);
}